// round 1
// baseline (speedup 1.0000x reference)
#include <cuda_runtime.h>
#include <math.h>

#define BB 4
#define NN 20000
#define EE 16
#define CC 128
#define BN (BB*NN)

#define NODES_PER_BLOCK 32
#define THREADS 256
#define WSTRIDE 132   // 128 + 4 pad: keeps 16B alignment, kills STS conflicts

// Scratch (no allocs allowed in kernel_launch)
__device__ float g_isd[BN];
__device__ float g_bufA[(size_t)BN * CC];
__device__ float g_bufB[(size_t)BN * CC];

// inv_sqrt_deg, layer-invariant
__global__ void isd_kernel(const int* __restrict__ edge) {
    int g = blockIdx.x * blockDim.x + threadIdx.x;
    if (g >= BN) return;
    const int* e = edge + (size_t)g * EE;
    int d = 1;
#pragma unroll
    for (int i = 0; i < EE; i++) d += (e[i] >= 0);
    g_isd[g] = rsqrtf((float)d);
}

__device__ __forceinline__ float elu(float v) {
    return v > 0.0f ? v : expm1f(v);
}

// One fused GCN layer:
//   u[n] = x[n]*isd[n] + sum_e x[nbr]*isd[nbr]
//   out[n] = ELU( isd[n] * (u[n] @ W^T) )
__global__ __launch_bounds__(THREADS, 2)
void layer_kernel(const float* __restrict__ xin,
                  const int*   __restrict__ edge,
                  const float* __restrict__ W,
                  float*       __restrict__ out)
{
    extern __shared__ float smem[];
    float* Ws = smem;                       // [CC][WSTRIDE]  transposed W
    float* us = smem + CC * WSTRIDE;        // [32][CC]       gathered u

    const int t    = threadIdx.x;
    const int warp = t >> 5;
    const int lane = t & 31;

    // Load W transposed: Ws[c][o] = W[o][c]
    for (int i = t; i < CC * CC; i += THREADS) {
        int o = i >> 7, c = i & 127;
        Ws[c * WSTRIDE + o] = W[i];
    }

    const int node0 = blockIdx.x * NODES_PER_BLOCK;

    // ---- Gather phase: warp w handles nodes node0 + 4w .. 4w+3 ----
#pragma unroll
    for (int i = 0; i < 4; i++) {
        const int gn = node0 + warp * 4 + i;      // global node (b*N+n)
        const int b  = gn / NN;
        const float sn = g_isd[gn];

        // lanes 0..15 fetch one neighbor's (index, isd) each
        int   eidx = 0;
        float es   = 0.0f;
        if (lane < EE) {
            int m = edge[(size_t)gn * EE + lane];
            if (m >= 0) { eidx = m; es = g_isd[b * NN + m]; }
        }

        const float* xb = xin + (size_t)b * NN * CC;
        float4 acc = *(const float4*)(xin + (size_t)gn * CC + lane * 4);
        acc.x *= sn; acc.y *= sn; acc.z *= sn; acc.w *= sn;

#pragma unroll
        for (int e = 0; e < EE; e++) {
            int   m = __shfl_sync(0xffffffffu, eidx, e);
            float s = __shfl_sync(0xffffffffu, es,   e);
            float4 v = *(const float4*)(xb + (size_t)m * CC + lane * 4);
            acc.x += v.x * s; acc.y += v.y * s;
            acc.z += v.z * s; acc.w += v.w * s;
        }
        // fold the second isd[n] scale into u
        acc.x *= sn; acc.y *= sn; acc.z *= sn; acc.w *= sn;
        *(float4*)(us + (warp * 4 + i) * CC + lane * 4) = acc;
    }
    __syncthreads();

    // ---- GEMV phase: warp w computes its own 4 nodes; lane owns
    //      outputs o = 4*lane .. 4*lane+3 (conflict-free LDS.128 on Ws) ----
    float acc[4][4];
#pragma unroll
    for (int i = 0; i < 4; i++)
#pragma unroll
        for (int j = 0; j < 4; j++) acc[i][j] = 0.0f;

    const float* u0 = us + (warp * 4 + 0) * CC;
    const float* u1 = us + (warp * 4 + 1) * CC;
    const float* u2 = us + (warp * 4 + 2) * CC;
    const float* u3 = us + (warp * 4 + 3) * CC;

    for (int c = 0; c < CC; c += 4) {
        float4 a0 = *(const float4*)(u0 + c);
        float4 a1 = *(const float4*)(u1 + c);
        float4 a2 = *(const float4*)(u2 + c);
        float4 a3 = *(const float4*)(u3 + c);
        const float uu[4][4] = {
            {a0.x, a0.y, a0.z, a0.w},
            {a1.x, a1.y, a1.z, a1.w},
            {a2.x, a2.y, a2.z, a2.w},
            {a3.x, a3.y, a3.z, a3.w}};
#pragma unroll
        for (int j = 0; j < 4; j++) {
            float4 wv = *(const float4*)(Ws + (c + j) * WSTRIDE + lane * 4);
#pragma unroll
            for (int i = 0; i < 4; i++) {
                acc[i][0] += uu[i][j] * wv.x;
                acc[i][1] += uu[i][j] * wv.y;
                acc[i][2] += uu[i][j] * wv.z;
                acc[i][3] += uu[i][j] * wv.w;
            }
        }
    }

#pragma unroll
    for (int i = 0; i < 4; i++) {
        const int gn = node0 + warp * 4 + i;
        float4 r;
        r.x = elu(acc[i][0]);
        r.y = elu(acc[i][1]);
        r.z = elu(acc[i][2]);
        r.w = elu(acc[i][3]);
        *(float4*)(out + (size_t)gn * CC + lane * 4) = r;
    }
}

extern "C" void kernel_launch(void* const* d_in, const int* in_sizes, int n_in,
                              void* d_out, int out_size) {
    const float* x    = (const float*)d_in[0];
    const int*   edge = (const int*)d_in[1];
    const float* W0   = (const float*)d_in[2];
    const float* W1   = (const float*)d_in[3];
    const float* W2   = (const float*)d_in[4];
    float* out = (float*)d_out;

    float *bufA = nullptr, *bufB = nullptr;
    cudaGetSymbolAddress((void**)&bufA, g_bufA);
    cudaGetSymbolAddress((void**)&bufB, g_bufB);

    const int smem_bytes = (CC * WSTRIDE + NODES_PER_BLOCK * CC) * sizeof(float);
    cudaFuncSetAttribute(layer_kernel,
                         cudaFuncAttributeMaxDynamicSharedMemorySize, smem_bytes);

    isd_kernel<<<(BN + 255) / 256, 256>>>(edge);

    const int blocks = BN / NODES_PER_BLOCK;   // 2500
    layer_kernel<<<blocks, THREADS, smem_bytes>>>(x,    edge, W0, bufA);
    layer_kernel<<<blocks, THREADS, smem_bytes>>>(bufA, edge, W1, bufB);
    layer_kernel<<<blocks, THREADS, smem_bytes>>>(bufB, edge, W2, out);
}

// round 2
// speedup vs baseline: 1.2821x; 1.2821x over previous
#include <cuda_runtime.h>
#include <math.h>

#define BB 4
#define NN 20000
#define EE 16
#define CC 128
#define BN (BB*NN)

#define THREADS 512
#define NODES_PER_BLOCK 64     // 16 warps x 4 nodes
#define WSTRIDE 132            // pad: conflict-free transpose STS

typedef unsigned long long u64;

// Scratch (no allocs allowed in kernel_launch)
__device__ float g_isd[BN];
__device__ float g_bufA[(size_t)BN * CC];
__device__ float g_bufB[(size_t)BN * CC];

union F4 { float4 v; u64 p[2]; float f[4]; };

__device__ __forceinline__ u64 fma2(u64 a, u64 b, u64 c) {
    u64 d; asm("fma.rn.f32x2 %0, %1, %2, %3;" : "=l"(d) : "l"(a), "l"(b), "l"(c));
    return d;
}
__device__ __forceinline__ u64 mul2(u64 a, u64 b) {
    u64 d; asm("mul.rn.f32x2 %0, %1, %2;" : "=l"(d) : "l"(a), "l"(b));
    return d;
}
__device__ __forceinline__ u64 dup2(float s) {
    u64 d; asm("mov.b64 %0, {%1, %1};" : "=l"(d) : "f"(s));
    return d;
}

// inv_sqrt_deg, layer-invariant
__global__ void isd_kernel(const int* __restrict__ edge) {
    int g = blockIdx.x * blockDim.x + threadIdx.x;
    if (g >= BN) return;
    const int* e = edge + (size_t)g * EE;
    int d = 1;
#pragma unroll
    for (int i = 0; i < EE; i++) d += (e[i] >= 0);
    g_isd[g] = rsqrtf((float)d);
}

__device__ __forceinline__ float elu(float v) {
    return v > 0.0f ? v : expm1f(v);
}

// One fused GCN layer:
//   u[n] = isd[n] * ( x[n]*isd[n] + sum_e x[nbr]*isd[nbr] )
//   out[n] = ELU( u[n] @ W^T )
__global__ __launch_bounds__(THREADS, 2)
void layer_kernel(const float* __restrict__ xin,
                  const int*   __restrict__ edge,
                  const float* __restrict__ W,
                  float*       __restrict__ out)
{
    extern __shared__ float smem[];
    float* Ws = smem;                       // [CC][WSTRIDE]  transposed W
    float* us = smem + CC * WSTRIDE;        // [64][CC]       gathered u

    const int t    = threadIdx.x;
    const int warp = t >> 5;
    const int lane = t & 31;

    // Load W transposed: Ws[c][o] = W[o][c]  (coalesced LDG, padded STS)
    for (int i = t; i < CC * CC; i += THREADS) {
        int o = i >> 7, c = i & 127;
        Ws[c * WSTRIDE + o] = W[i];
    }

    const int node0 = blockIdx.x * NODES_PER_BLOCK;

    // ---- Gather: warp w handles nodes node0 + 4w .. 4w+3 ----
#pragma unroll
    for (int i = 0; i < 4; i++) {
        const int gn = node0 + warp * 4 + i;
        const int b  = gn / NN;
        const float sn = g_isd[gn];

        int   eidx = 0;
        float es   = 0.0f;
        if (lane < EE) {
            int m = edge[(size_t)gn * EE + lane];
            if (m >= 0) { eidx = m; es = g_isd[b * NN + m]; }
        }

        const float* xb = xin + (size_t)b * NN * CC;

        F4 self; self.v = *(const float4*)(xin + (size_t)gn * CC + lane * 4);
        u64 snd = dup2(sn);
        u64 a0 = mul2(self.p[0], snd);
        u64 a1 = mul2(self.p[1], snd);

#pragma unroll 4
        for (int e = 0; e < EE; e++) {
            int   m = __shfl_sync(0xffffffffu, eidx, e);
            float s = __shfl_sync(0xffffffffu, es,   e);
            F4 v; v.v = *(const float4*)(xb + (size_t)m * CC + lane * 4);
            u64 sd = dup2(s);
            a0 = fma2(v.p[0], sd, a0);
            a1 = fma2(v.p[1], sd, a1);
        }
        // fold second isd[n]
        a0 = mul2(a0, snd);
        a1 = mul2(a1, snd);
        F4 r; r.p[0] = a0; r.p[1] = a1;
        *(float4*)(us + (warp * 4 + i) * CC + lane * 4) = r.v;
    }
    __syncthreads();

    // ---- GEMV: warp computes its 4 nodes; lane owns outputs 4*lane..+3 ----
    u64 a01[4], a23[4];
#pragma unroll
    for (int i = 0; i < 4; i++) { a01[i] = 0ull; a23[i] = 0ull; }

    const float* ub = us + (warp * 4) * CC;

    for (int c = 0; c < CC; c += 4) {
        F4 u[4];
#pragma unroll
        for (int i = 0; i < 4; i++)
            u[i].v = *(const float4*)(ub + i * CC + c);   // broadcast LDS
#pragma unroll
        for (int j = 0; j < 4; j++) {
            F4 w; w.v = *(const float4*)(Ws + (c + j) * WSTRIDE + lane * 4);
#pragma unroll
            for (int i = 0; i < 4; i++) {
                u64 d = dup2(u[i].f[j]);
                a01[i] = fma2(w.p[0], d, a01[i]);
                a23[i] = fma2(w.p[1], d, a23[i]);
            }
        }
    }

#pragma unroll
    for (int i = 0; i < 4; i++) {
        const int gn = node0 + warp * 4 + i;
        F4 r0; r0.p[0] = a01[i]; r0.p[1] = a23[i];
        F4 r;
        r.f[0] = elu(r0.f[0]);
        r.f[1] = elu(r0.f[1]);
        r.f[2] = elu(r0.f[2]);
        r.f[3] = elu(r0.f[3]);
        *(float4*)(out + (size_t)gn * CC + lane * 4) = r.v;
    }
}

extern "C" void kernel_launch(void* const* d_in, const int* in_sizes, int n_in,
                              void* d_out, int out_size) {
    const float* x    = (const float*)d_in[0];
    const int*   edge = (const int*)d_in[1];
    const float* W0   = (const float*)d_in[2];
    const float* W1   = (const float*)d_in[3];
    const float* W2   = (const float*)d_in[4];
    float* out = (float*)d_out;

    float *bufA = nullptr, *bufB = nullptr;
    cudaGetSymbolAddress((void**)&bufA, g_bufA);
    cudaGetSymbolAddress((void**)&bufB, g_bufB);

    const int smem_bytes = (CC * WSTRIDE + NODES_PER_BLOCK * CC) * sizeof(float);
    cudaFuncSetAttribute(layer_kernel,
                         cudaFuncAttributeMaxDynamicSharedMemorySize, smem_bytes);

    isd_kernel<<<(BN + 255) / 256, 256>>>(edge);

    const int blocks = BN / NODES_PER_BLOCK;   // 1250
    layer_kernel<<<blocks, THREADS, smem_bytes>>>(x,    edge, W0, bufA);
    layer_kernel<<<blocks, THREADS, smem_bytes>>>(bufA, edge, W1, bufB);
    layer_kernel<<<blocks, THREADS, smem_bytes>>>(bufB, edge, W2, out);
}

// round 3
// speedup vs baseline: 1.3974x; 1.0900x over previous
#include <cuda_runtime.h>
#include <math.h>

#define BB 4
#define NN 20000
#define EE 16
#define CC 128
#define BN (BB*NN)

#define THREADS 256
#define NPW 8                       // nodes per warp
#define NODES_PER_BLOCK 64          // 8 warps x 8 nodes
#define WSTRIDE 132                 // pad: conflict-free LDS/STS

typedef unsigned long long u64;

// Scratch (no allocs allowed). +1 row of zeros at index BN (pad for -1 edges).
__device__ float g_isd[BN];
__device__ float g_bufA[((size_t)BN + 1) * CC];
__device__ float g_bufB[((size_t)BN + 1) * CC];

union F4 { float4 v; u64 p[2]; float f[4]; };

__device__ __forceinline__ u64 fma2(u64 a, u64 b, u64 c) {
    u64 d; asm("fma.rn.f32x2 %0, %1, %2, %3;" : "=l"(d) : "l"(a), "l"(b), "l"(c));
    return d;
}
__device__ __forceinline__ u64 add2(u64 a, u64 b) {
    u64 d; asm("add.rn.f32x2 %0, %1, %2;" : "=l"(d) : "l"(a), "l"(b));
    return d;
}
__device__ __forceinline__ u64 mul2(u64 a, u64 b) {
    u64 d; asm("mul.rn.f32x2 %0, %1, %2;" : "=l"(d) : "l"(a), "l"(b));
    return d;
}
__device__ __forceinline__ u64 dup2(float s) {
    u64 d; asm("mov.b64 %0, {%1, %1};" : "=l"(d) : "f"(s));
    return d;
}
__device__ __forceinline__ float elu(float v) {
    return v > 0.0f ? v : expm1f(v);
}

// inv_sqrt_deg, layer-invariant
__global__ void isd_kernel(const int* __restrict__ edge) {
    int g = blockIdx.x * blockDim.x + threadIdx.x;
    if (g >= BN) return;
    const int* e = edge + (size_t)g * EE;
    int d = 1;
#pragma unroll
    for (int i = 0; i < EE; i++) d += (e[i] >= 0);
    g_isd[g] = rsqrtf((float)d);
}

// z0 = x * isd (row-scaled); also zero the pad rows of both buffers.
__global__ void zprep_kernel(const float* __restrict__ x) {
    int t = blockIdx.x * blockDim.x + threadIdx.x;   // one float4 per thread
    if (t < BN * (CC / 4)) {
        int row = t >> 5;          // CC/4 = 32
        float s = g_isd[row];
        F4 v; v.v = *(const float4*)(x + (size_t)t * 4);
        u64 sd = dup2(s);
        v.p[0] = mul2(v.p[0], sd);
        v.p[1] = mul2(v.p[1], sd);
        *(float4*)(g_bufA + (size_t)t * 4) = v.v;
    } else {
        int r = t - BN * (CC / 4);
        if (r < CC / 4) {
            *(float4*)(g_bufA + (size_t)BN * CC + r * 4) = make_float4(0, 0, 0, 0);
            *(float4*)(g_bufB + (size_t)BN * CC + r * 4) = make_float4(0, 0, 0, 0);
        }
    }
}

// One fused GCN layer on pre-scaled z:
//   u[n]   = isd[n] * ( z[n] + sum_e z[nbr] )
//   v[n]   = u[n] @ W^T
//   out[n] = LAST ? ELU(v) : ELU(v) * isd[n]     (z for next layer)
template<bool LAST>
__global__ __launch_bounds__(THREADS, 2)
void layer_kernel(const float* __restrict__ zin,
                  const int*   __restrict__ edge,
                  const float* __restrict__ W,
                  float*       __restrict__ out)
{
    extern __shared__ float smem[];
    float* Ws = smem;                       // [CC][WSTRIDE]  transposed W
    float* us = smem + CC * WSTRIDE;        // [64][CC]

    const int t    = threadIdx.x;
    const int warp = t >> 5;
    const int lane = t & 31;

    // W transposed: Ws[c][o] = W[o][c]
    for (int i = t; i < CC * CC; i += THREADS) {
        int o = i >> 7, c = i & 127;
        Ws[c * WSTRIDE + o] = W[i];
    }

    const int node0 = blockIdx.x * NODES_PER_BLOCK + warp * NPW;

    // ---- Gather: pure sum of pre-scaled rows ----
    int  eidx[NPW];          // lane<16: edge e=lane of node i (global row, pad->BN)
    F4   acc[NPW];
    int  rowbase[NPW];
#pragma unroll
    for (int i = 0; i < NPW; i++) {
        const int gn = node0 + i;
        rowbase[i] = (gn / NN) * NN;
        int m = -1;
        if (lane < EE) m = edge[(size_t)gn * EE + lane];
        eidx[i] = (m < 0) ? BN : (rowbase[i] + m);
        acc[i].v = *(const float4*)(zin + (size_t)gn * CC + lane * 4);
    }

#pragma unroll 4
    for (int e = 0; e < EE; e++) {
#pragma unroll
        for (int i = 0; i < NPW; i++) {
            int m = __shfl_sync(0xffffffffu, eidx[i], e);
            F4 v; v.v = *(const float4*)(zin + (size_t)m * CC + lane * 4);
            acc[i].p[0] = add2(acc[i].p[0], v.p[0]);
            acc[i].p[1] = add2(acc[i].p[1], v.p[1]);
        }
    }

#pragma unroll
    for (int i = 0; i < NPW; i++) {
        const int gn = node0 + i;
        u64 sd = dup2(g_isd[gn]);
        acc[i].p[0] = mul2(acc[i].p[0], sd);
        acc[i].p[1] = mul2(acc[i].p[1], sd);
        *(float4*)(us + (warp * NPW + i) * CC + lane * 4) = acc[i].v;
    }
    __syncthreads();

    // ---- GEMV: warp computes its 8 nodes; lane owns outputs 4*lane..+3 ----
    u64 a01[NPW], a23[NPW];
#pragma unroll
    for (int i = 0; i < NPW; i++) { a01[i] = 0ull; a23[i] = 0ull; }

    const float* ub = us + (warp * NPW) * CC;

    for (int c = 0; c < CC; c += 4) {
        F4 u[NPW];
#pragma unroll
        for (int i = 0; i < NPW; i++)
            u[i].v = *(const float4*)(ub + i * CC + c);   // broadcast LDS
#pragma unroll
        for (int j = 0; j < 4; j++) {
            F4 w; w.v = *(const float4*)(Ws + (c + j) * WSTRIDE + lane * 4);
#pragma unroll
            for (int i = 0; i < NPW; i++) {
                u64 d = dup2(u[i].f[j]);
                a01[i] = fma2(w.p[0], d, a01[i]);
                a23[i] = fma2(w.p[1], d, a23[i]);
            }
        }
    }

#pragma unroll
    for (int i = 0; i < NPW; i++) {
        const int gn = node0 + i;
        F4 r0; r0.p[0] = a01[i]; r0.p[1] = a23[i];
        F4 r;
        r.f[0] = elu(r0.f[0]);
        r.f[1] = elu(r0.f[1]);
        r.f[2] = elu(r0.f[2]);
        r.f[3] = elu(r0.f[3]);
        if (!LAST) {
            u64 sd = dup2(g_isd[gn]);
            r.p[0] = mul2(r.p[0], sd);
            r.p[1] = mul2(r.p[1], sd);
        }
        *(float4*)(out + (size_t)gn * CC + lane * 4) = r.v;
    }
}

extern "C" void kernel_launch(void* const* d_in, const int* in_sizes, int n_in,
                              void* d_out, int out_size) {
    const float* x    = (const float*)d_in[0];
    const int*   edge = (const int*)d_in[1];
    const float* W0   = (const float*)d_in[2];
    const float* W1   = (const float*)d_in[3];
    const float* W2   = (const float*)d_in[4];
    float* out = (float*)d_out;

    float *bufA = nullptr, *bufB = nullptr;
    cudaGetSymbolAddress((void**)&bufA, g_bufA);
    cudaGetSymbolAddress((void**)&bufB, g_bufB);

    const int smem_bytes = (CC * WSTRIDE + NODES_PER_BLOCK * CC) * sizeof(float);
    cudaFuncSetAttribute(layer_kernel<false>,
                         cudaFuncAttributeMaxDynamicSharedMemorySize, smem_bytes);
    cudaFuncSetAttribute(layer_kernel<true>,
                         cudaFuncAttributeMaxDynamicSharedMemorySize, smem_bytes);

    isd_kernel<<<(BN + 255) / 256, 256>>>(edge);

    // z0 = x*isd -> bufA ; zero pad rows
    const int zthreads = BN * (CC / 4) + (CC / 4);
    zprep_kernel<<<(zthreads + 255) / 256, 256>>>(x);

    const int blocks = BN / NODES_PER_BLOCK;   // 1250
    layer_kernel<false><<<blocks, THREADS, smem_bytes>>>(bufA, edge, W0, bufB);
    layer_kernel<false><<<blocks, THREADS, smem_bytes>>>(bufB, edge, W1, bufA);
    layer_kernel<true ><<<blocks, THREADS, smem_bytes>>>(bufA, edge, W2, out);
}

// round 5
// speedup vs baseline: 1.4050x; 1.0054x over previous
#include <cuda_runtime.h>
#include <math.h>

#define BB 4
#define NN 20000
#define EE 16
#define CC 128
#define BN (BB*NN)

#define THREADS 512
#define NWARPS 16
#define MW 6                     // nodes per warp
#define NPB (NWARPS*MW)          // 96 nodes per CTA

typedef unsigned long long u64;

// Scratch (+1 zero pad row at index BN for -1 edges)
__device__ float g_isd[BN];
__device__ float g_bufA[((size_t)BN + 1) * CC];
__device__ float g_bufB[((size_t)BN + 1) * CC];
__device__ float g_Wt[3][CC * CC];   // pre-transposed: Wt[c*128+o] = W[o*128+c]

union F4 { float4 v; u64 p[2]; float f[4]; };

__device__ __forceinline__ u64 fma2(u64 a, u64 b, u64 c) {
    u64 d; asm("fma.rn.f32x2 %0,%1,%2,%3;" : "=l"(d) : "l"(a), "l"(b), "l"(c)); return d;
}
__device__ __forceinline__ u64 add2(u64 a, u64 b) {
    u64 d; asm("add.rn.f32x2 %0,%1,%2;" : "=l"(d) : "l"(a), "l"(b)); return d;
}
__device__ __forceinline__ u64 mul2(u64 a, u64 b) {
    u64 d; asm("mul.rn.f32x2 %0,%1,%2;" : "=l"(d) : "l"(a), "l"(b)); return d;
}
__device__ __forceinline__ u64 dup2(float s) {
    u64 d; asm("mov.b64 %0,{%1,%1};" : "=l"(d) : "f"(s)); return d;
}
__device__ __forceinline__ float elu(float v) { return v > 0.0f ? v : expm1f(v); }

// ---- prep kernels ----
__global__ void isd_kernel(const int* __restrict__ edge) {
    int g = blockIdx.x * blockDim.x + threadIdx.x;
    if (g >= BN) return;
    const int* e = edge + (size_t)g * EE;
    int d = 1;
#pragma unroll
    for (int i = 0; i < EE; i++) d += (e[i] >= 0);
    g_isd[g] = rsqrtf((float)d);
}

// z0 = x * isd -> bufA; zero pad rows of both buffers
__global__ void zprep_kernel(const float* __restrict__ x) {
    int t = blockIdx.x * blockDim.x + threadIdx.x;   // one float4 per thread
    if (t < BN * (CC / 4)) {
        int row = t >> 5;
        float s = g_isd[row];
        F4 v; v.v = *(const float4*)(x + (size_t)t * 4);
        u64 sd = dup2(s);
        v.p[0] = mul2(v.p[0], sd);
        v.p[1] = mul2(v.p[1], sd);
        *(float4*)(g_bufA + (size_t)t * 4) = v.v;
    } else {
        int r = t - BN * (CC / 4);
        if (r < CC / 4) {
            *(float4*)(g_bufA + (size_t)BN * CC + r * 4) = make_float4(0, 0, 0, 0);
            *(float4*)(g_bufB + (size_t)BN * CC + r * 4) = make_float4(0, 0, 0, 0);
        }
    }
}

// Transpose all three W's once: Wt[l][c*128+o] = W_l[o*128+c]
__global__ void wtrans_kernel(const float* __restrict__ W0,
                              const float* __restrict__ W1,
                              const float* __restrict__ W2) {
    int t = blockIdx.x * blockDim.x + threadIdx.x;
    if (t >= 3 * CC * CC) return;
    int l = t / (CC * CC), i = t % (CC * CC);
    int c = i >> 7, o = i & 127;
    const float* W = (l == 0) ? W0 : (l == 1) ? W1 : W2;
    g_Wt[l][i] = W[o * CC + c];
}

// ---- fused layer ----
// u[n]   = isd[n] * ( z[n] + sum_e z[nbr] )          (z pre-scaled by isd)
// v[n]   = u[n] @ W^T
// out[n] = LAST ? ELU(v) : ELU(v) * isd[n]
template<bool LAST>
__global__ __launch_bounds__(THREADS, 2)
void layer_kernel(const float* __restrict__ zin,
                  const int*   __restrict__ edge,
                  const float* __restrict__ Wt,     // pre-transposed [c][o]
                  float*       __restrict__ out)
{
    extern __shared__ float sm[];
    float* Ws = sm;                   // [128][128] transposed W (64 KB)
    float* us = sm + CC * CC;         // [96][128]  gathered u   (48 KB)

    const int t = threadIdx.x, w = t >> 5, lane = t & 31;

    // Stage W: pure coalesced float4 copy (conflict-free STS + later LDS)
    {
        const float4* src = (const float4*)Wt;
        float4* dst = (float4*)Ws;
#pragma unroll
        for (int i = 0; i < (CC * CC / 4) / THREADS; i++)
            dst[t + i * THREADS] = src[t + i * THREADS];
    }

    const int node0 = blockIdx.x * NPB + w * MW;

    // ---- Gather: warp handles 6 nodes; lane owns channels [4*lane, 4*lane+4) ----
    F4    acc[MW];
    int   eidx[MW];
    float sn[MW];
#pragma unroll
    for (int i = 0; i < MW; i++) {
        const int gn = node0 + i;
        const bool valid = (gn < BN);
        const int gi = valid ? gn : BN;               // pad row (zeros)
        sn[i] = g_isd[valid ? gn : 0];
        int m = -1;
        if (valid && lane < EE) m = edge[(size_t)gn * EE + lane];
        const int base = valid ? (gn / NN) * NN : 0;
        eidx[i] = (m < 0) ? BN : (base + m);
        acc[i].v = *(const float4*)(zin + (size_t)gi * CC + lane * 4);
    }

#pragma unroll 4
    for (int e = 0; e < EE; e++) {
#pragma unroll
        for (int i = 0; i < MW; i++) {
            int m = __shfl_sync(0xffffffffu, eidx[i], e);
            F4 v; v.v = *(const float4*)(zin + (size_t)m * CC + lane * 4);
            acc[i].p[0] = add2(acc[i].p[0], v.p[0]);
            acc[i].p[1] = add2(acc[i].p[1], v.p[1]);
        }
    }

#pragma unroll
    for (int i = 0; i < MW; i++) {
        u64 sd = dup2(sn[i]);
        acc[i].p[0] = mul2(acc[i].p[0], sd);
        acc[i].p[1] = mul2(acc[i].p[1], sd);
        *(float4*)(us + (w * MW + i) * CC + lane * 4) = acc[i].v;
    }
    __syncthreads();

    // ---- GEMV: warp computes its own 6 nodes; lane owns outputs 4*lane..+3 ----
    u64 a01[MW], a23[MW];
#pragma unroll
    for (int i = 0; i < MW; i++) { a01[i] = 0ull; a23[i] = 0ull; }

    const float* ub = us + (w * MW) * CC;

    for (int c = 0; c < CC; c += 4) {
        F4 u[MW];
#pragma unroll
        for (int i = 0; i < MW; i++)
            u[i].v = *(const float4*)(ub + i * CC + c);     // broadcast LDS.128
#pragma unroll
        for (int j = 0; j < 4; j++) {
            F4 wv; wv.v = *(const float4*)(Ws + (c + j) * CC + lane * 4);
#pragma unroll
            for (int i = 0; i < MW; i++) {
                u64 d = dup2(u[i].f[j]);
                a01[i] = fma2(wv.p[0], d, a01[i]);
                a23[i] = fma2(wv.p[1], d, a23[i]);
            }
        }
    }

    // ---- Epilogue ----
#pragma unroll
    for (int i = 0; i < MW; i++) {
        const int gn = node0 + i;
        if (gn >= BN) continue;
        F4 r0; r0.p[0] = a01[i]; r0.p[1] = a23[i];
        F4 r;
        r.f[0] = elu(r0.f[0]);
        r.f[1] = elu(r0.f[1]);
        r.f[2] = elu(r0.f[2]);
        r.f[3] = elu(r0.f[3]);
        if (!LAST) {
            u64 sd = dup2(sn[i]);
            r.p[0] = mul2(r.p[0], sd);
            r.p[1] = mul2(r.p[1], sd);
        }
        *(float4*)(out + (size_t)gn * CC + lane * 4) = r.v;
    }
}

extern "C" void kernel_launch(void* const* d_in, const int* in_sizes, int n_in,
                              void* d_out, int out_size) {
    const float* x    = (const float*)d_in[0];
    const int*   edge = (const int*)d_in[1];
    const float* W0   = (const float*)d_in[2];
    const float* W1   = (const float*)d_in[3];
    const float* W2   = (const float*)d_in[4];
    float* out = (float*)d_out;

    float *bufA = nullptr, *bufB = nullptr, *Wt = nullptr;
    cudaGetSymbolAddress((void**)&bufA, g_bufA);
    cudaGetSymbolAddress((void**)&bufB, g_bufB);
    cudaGetSymbolAddress((void**)&Wt,   g_Wt);

    const int smem_bytes = (CC * CC + NPB * CC) * sizeof(float);   // 114688
    cudaFuncSetAttribute(layer_kernel<false>,
                         cudaFuncAttributeMaxDynamicSharedMemorySize, smem_bytes);
    cudaFuncSetAttribute(layer_kernel<true>,
                         cudaFuncAttributeMaxDynamicSharedMemorySize, smem_bytes);

    isd_kernel<<<(BN + 255) / 256, 256>>>(edge);

    const int zthreads = BN * (CC / 4) + (CC / 4);
    zprep_kernel<<<(zthreads + 255) / 256, 256>>>(x);

    wtrans_kernel<<<(3 * CC * CC + 255) / 256, 256>>>(W0, W1, W2);

    const int blocks = (BN + NPB - 1) / NPB;   // 834
    layer_kernel<false><<<blocks, THREADS, smem_bytes>>>(bufA, edge, Wt + 0 * CC * CC, bufB);
    layer_kernel<false><<<blocks, THREADS, smem_bytes>>>(bufB, edge, Wt + 1 * CC * CC, bufA);
    layer_kernel<true ><<<blocks, THREADS, smem_bytes>>>(bufA, edge, Wt + 2 * CC * CC, out);
}